// round 12
// baseline (speedup 1.0000x reference)
#include <cuda_runtime.h>
#include <cstdint>

#define BB 16
#define CC 80
#define TX 512
#define TY 2048
#define NEGF (-1000000000.0f)

// Output layout (flat concat, fp32):
// z_T [B,TY,C], y_mean_T [B,TY,C], y_ls_T [B,TY,C], attn_T [B,TY,TX], dur [B,TX,1]
#define N_ZT   ((size_t)BB * TY * CC)
#define OFF_Z   ((size_t)0)
#define OFF_M   (N_ZT)
#define OFF_L   (2 * N_ZT)
#define OFF_AT  (3 * N_ZT)
#define OFF_DUR (3 * N_ZT + (size_t)BB * TY * TX)

// ---------------- scratch ----------------
__device__ float g_a   [BB * CC * TX];
__device__ float g_ms  [BB * CC * TX];
__device__ float g_bias[BB * TX];
__device__ float g_logp[(size_t)BB * TY * TX];
__device__ int   g_xs  [BB * TY];
__device__ float g_omT [BB * TX * CC];   // [b][x][c]
__device__ float g_olsT[BB * TX * CC];

// ---------------- f32x2 helpers ----------------
__device__ __forceinline__ unsigned long long pack2(float lo, float hi) {
    unsigned long long r;
    asm("mov.b64 %0, {%1, %2};" : "=l"(r) : "f"(lo), "f"(hi));
    return r;
}
__device__ __forceinline__ float2 unpack2(unsigned long long v) {
    float lo, hi;
    asm("mov.b64 {%0, %1}, %2;" : "=f"(lo), "=f"(hi) : "l"(v));
    return make_float2(lo, hi);
}
__device__ __forceinline__ unsigned long long fma2(unsigned long long a,
                                                   unsigned long long b,
                                                   unsigned long long c) {
    unsigned long long d;
    asm("fma.rn.f32x2 %0, %1, %2, %3;" : "=l"(d) : "l"(a), "l"(b), "l"(c));
    return d;
}
__device__ __forceinline__ unsigned swz(unsigned b) {
    return b ^ ((b >> 3) & 0x70u);
}
__device__ __forceinline__ void cp16(unsigned smem_addr, const void* gptr) {
    asm volatile("cp.async.ca.shared.global [%0], [%1], 16;\n"
                 :: "r"(smem_addr), "l"(gptr));
}
#define CP_COMMIT() asm volatile("cp.async.commit_group;\n" ::: "memory")
#define CP_WAIT(n)  asm volatile("cp.async.wait_group %0;\n" :: "n"(n) : "memory")

// ---------------- kernel 1: prep ----------------
__global__ void __launch_bounds__(128) prep_kernel(const float* __restrict__ om,
                                                   const float* __restrict__ ols) {
    int b = blockIdx.y;
    int x = blockIdx.x * 128 + threadIdx.x;
    float acc = 0.0f;
    for (int c = 0; c < CC; ++c) {
        size_t i = ((size_t)b * CC + c) * TX + x;
        float ls = ols[i];
        float m  = om[i];
        float a  = expf(-2.0f * ls);
        g_a[i]  = a;
        g_ms[i] = m * a;
        acc += -0.9189385332046727f - ls - 0.5f * m * m * a;
    }
    g_bias[b * TX + x] = acc;
}

// ---------------- kernel 2: pre_out (transposes + attn zero-fill) ----------------
#define NFILL 112
__global__ void __launch_bounds__(512) pre_out(const float* __restrict__ z,
                                               const float* __restrict__ om,
                                               const float* __restrict__ ols,
                                               const int* __restrict__ ylen,
                                               float* __restrict__ out) {
    __shared__ float tile[CC * 129];
    int bid = blockIdx.x;
    int tid = threadIdx.x;
    if (bid < 384) {
        int role, idx;
        const float* src;
        int srcN;
        if (bid < 256)      { role = 0; idx = bid;       src = z;   srcN = TY; }
        else if (bid < 320) { role = 1; idx = bid - 256; src = om;  srcN = TX; }
        else                { role = 2; idx = bid - 320; src = ols; srcN = TX; }
        int tilesPerB = (role == 0) ? 16 : 4;
        int b  = idx / tilesPerB;
        int n0 = (idx % tilesPerB) * 128;
        int tyL = ylen[b];
#pragma unroll
        for (int i = 0; i < 5; ++i) {
            int f  = tid + i * 512;
            int c  = f >> 5;
            int s4 = (f & 31) << 2;
            float4 v = *(const float4*)&src[((size_t)b * CC + c) * srcN + n0 + s4];
            int base = c * 129 + s4;
            tile[base]     = v.x;
            tile[base + 1] = v.y;
            tile[base + 2] = v.z;
            tile[base + 3] = v.w;
        }
        __syncthreads();
#pragma unroll
        for (int i = 0; i < 5; ++i) {
            int f  = tid + i * 512;
            int sl = f / 20;
            int c4 = (f % 20) * 4;
            float4 o;
            o.x = tile[(c4 + 0) * 129 + sl];
            o.y = tile[(c4 + 1) * 129 + sl];
            o.z = tile[(c4 + 2) * 129 + sl];
            o.w = tile[(c4 + 3) * 129 + sl];
            int n = n0 + sl;
            if (role == 0) {
                if (n >= tyL) o = make_float4(0.f, 0.f, 0.f, 0.f);
                *(float4*)&out[OFF_Z + ((size_t)b * TY + n) * CC + c4] = o;
            } else {
                float* dst = (role == 1) ? g_omT : g_olsT;
                *(float4*)&dst[((size_t)b * TX + n) * CC + c4] = o;
            }
        }
    } else {
        size_t total = (size_t)BB * TY * TX / 4;
        float4* p = (float4*)&out[OFF_AT];
        float4 zv = make_float4(0.f, 0.f, 0.f, 0.f);
        size_t start = (size_t)(bid - 384) * 512 + tid;
        for (size_t i = start; i < total; i += (size_t)NFILL * 512)
            p[i] = zv;
    }
}

// ---------------- kernel 3: logp GEMM (f32x2, dup-A smem, 128x128 tile) ----------------
#define GEMM_SMEM 49152
__global__ void __launch_bounds__(256, 2) gemm_logp(const float* __restrict__ z,
                                                    const int* __restrict__ xlen,
                                                    const int* __restrict__ ylen) {
    extern __shared__ __align__(16) unsigned char gsm[];
    unsigned char* smA  = gsm;
    unsigned char* smM  = gsm + 16384;
    unsigned char* smZ1 = gsm + 32768;
    unsigned char* smZ2 = gsm + 40960;

    int b  = blockIdx.z;
    int x0 = blockIdx.x * 128;
    int y0 = blockIdx.y * 128;
    int tid = threadIdx.x;
    int txi = tid & 15;
    int tyi = tid >> 4;
    int xl = txi * 8;
    int yl = tyi * 8;

    unsigned aoff[4];
#pragma unroll
    for (int g = 0; g < 4; ++g) aoff[g] = swz((unsigned)(txi * 64 + g * 16));
    unsigned zoff = (unsigned)(tyi * 32);

    unsigned long long acc[8][4];   // [x_local][y_pair]
#pragma unroll
    for (int i = 0; i < 8; ++i)
#pragma unroll
        for (int j = 0; j < 4; ++j) acc[i][j] = 0ULL;

    for (int kc = 0; kc < CC; kc += 16) {
        __syncthreads();
#pragma unroll
        for (int i = 0; i < 2; ++i) {
            int f  = tid + i * 256;
            int r  = f >> 5;
            int c4 = (f & 31) << 2;
            size_t gi = ((size_t)b * CC + kc + r) * TX + x0 + c4;
            float4 av = *(const float4*)&g_a[gi];
            float4 mv = *(const float4*)&g_ms[gi];
            unsigned sb0 = swz((unsigned)(c4 * 8));
            unsigned sb1 = swz((unsigned)(c4 * 8 + 16));
            *(ulonglong2*)(smA + r * 1024 + sb0) = make_ulonglong2(pack2(av.x, av.x), pack2(av.y, av.y));
            *(ulonglong2*)(smA + r * 1024 + sb1) = make_ulonglong2(pack2(av.z, av.z), pack2(av.w, av.w));
            *(ulonglong2*)(smM + r * 1024 + sb0) = make_ulonglong2(pack2(mv.x, mv.x), pack2(mv.y, mv.y));
            *(ulonglong2*)(smM + r * 1024 + sb1) = make_ulonglong2(pack2(mv.z, mv.z), pack2(mv.w, mv.w));
        }
#pragma unroll
        for (int i = 0; i < 2; ++i) {
            int f  = tid + i * 256;
            int r  = f >> 5;
            int c4 = (f & 31) << 2;
            size_t gi = ((size_t)b * CC + kc + r) * TY + y0 + c4;
            float4 zv = *(const float4*)&z[gi];
            ulonglong2* p1 = (ulonglong2*)(smZ1 + r * 512 + (f & 31) * 16);
            ulonglong2* p2 = (ulonglong2*)(smZ2 + r * 512 + (f & 31) * 16);
            *p1 = make_ulonglong2(pack2(zv.x, zv.y), pack2(zv.z, zv.w));
            *p2 = make_ulonglong2(pack2(-0.5f * zv.x * zv.x, -0.5f * zv.y * zv.y),
                                  pack2(-0.5f * zv.z * zv.z, -0.5f * zv.w * zv.w));
        }
        __syncthreads();
#pragma unroll
        for (int k = 0; k < 16; ++k) {
            const unsigned char* rowA = smA + k * 1024;
            const unsigned char* rowM = smM + k * 1024;
            ulonglong2 z1a = *(const ulonglong2*)(smZ1 + k * 512 + zoff);
            ulonglong2 z1b = *(const ulonglong2*)(smZ1 + k * 512 + zoff + 16);
            ulonglong2 z2a = *(const ulonglong2*)(smZ2 + k * 512 + zoff);
            ulonglong2 z2b = *(const ulonglong2*)(smZ2 + k * 512 + zoff + 16);
            unsigned long long z1p[4] = {z1a.x, z1a.y, z1b.x, z1b.y};
            unsigned long long z2p[4] = {z2a.x, z2a.y, z2b.x, z2b.y};
#pragma unroll
            for (int g = 0; g < 4; ++g) {
                ulonglong2 a2 = *(const ulonglong2*)(rowA + aoff[g]);
                ulonglong2 m2 = *(const ulonglong2*)(rowM + aoff[g]);
#pragma unroll
                for (int yp = 0; yp < 4; ++yp) {
                    acc[2 * g][yp]     = fma2(a2.x, z2p[yp], acc[2 * g][yp]);
                    acc[2 * g][yp]     = fma2(m2.x, z1p[yp], acc[2 * g][yp]);
                    acc[2 * g + 1][yp] = fma2(a2.y, z2p[yp], acc[2 * g + 1][yp]);
                    acc[2 * g + 1][yp] = fma2(m2.y, z1p[yp], acc[2 * g + 1][yp]);
                }
            }
        }
    }

    int txL = xlen[b], tyL = ylen[b];
    float bv[8];
    *(float4*)&bv[0] = *(const float4*)&g_bias[b * TX + x0 + xl];
    *(float4*)&bv[4] = *(const float4*)&g_bias[b * TX + x0 + xl + 4];
#pragma unroll
    for (int yy = 0; yy < 8; ++yy) {
        int y = y0 + yl + yy;
        bool yok = (y < tyL);
        int yp = yy >> 1;
        bool hi = (yy & 1);
        float o[8];
#pragma unroll
        for (int j = 0; j < 8; ++j) {
            float2 u = unpack2(acc[j][yp]);
            float v = hi ? u.y : u.x;
            int x = x0 + xl + j;
            o[j] = (yok && x < txL) ? (bv[j] + v) : 0.0f;
        }
        size_t base = ((size_t)b * TY + y) * TX + x0 + xl;
        *(float4*)&g_logp[base]     = make_float4(o[0], o[1], o[2], o[3]);
        *(float4*)&g_logp[base + 4] = make_float4(o[4], o[5], o[6], o[7]);
    }
}

// ---------------- kernel 4: DP forward (4-warp systolic, 2 columns per shfl round) ----------------
// smem: sd[TY/8][128] u32 128KB | bndw[4][64] 1KB | sxs[TY] 8KB | ring[16][128] float4 32KB
#define DPW 4
#define CHUNK 16
#define RINGC 16
#define SD_WORDS (TY / 8 * 128)
#define FWD_SMEM (SD_WORDS * 4 + DPW * 64 * 4 + TY * 4 + RINGC * 128 * 16)

__global__ void __launch_bounds__(128) fwd_kernel(const int* __restrict__ xlen,
                                                  const int* __restrict__ ylen,
                                                  float* __restrict__ out) {
    extern __shared__ unsigned char fsm[];
    unsigned* sd = (unsigned*)fsm;                                     // [TY/8][128]
    float* bndw = (float*)(fsm + (size_t)SD_WORDS * 4);                // [DPW][64] circular
    int* sxs = (int*)(fsm + (size_t)SD_WORDS * 4 + DPW * 64 * 4);      // [TY]
    float4* ring = (float4*)(fsm + (size_t)SD_WORDS * 4 + DPW * 64 * 4 + TY * 4);

    int b = blockIdx.x;
    int tid = threadIdx.x;
    int w = tid >> 5, lane = tid & 31;
    const float4* lp4 = (const float4*)&g_logp[(size_t)b * TY * TX];
    int gx0 = tid * 4;
    float* mybnd = bndw + w * 64;
    const float* pbnd = bndw + (w - 1) * 64;

    unsigned rbase = (unsigned)__cvta_generic_to_shared(ring) + tid * 16;
    int tprev = (tid > 0) ? tid - 1 : 0;     // neighbor lane's ring slot (tid==0 value unused)

    // prime: 2 groups of 8 columns
#pragma unroll
    for (int d = 0; d < 2; ++d) {
#pragma unroll
        for (int q = 0; q < 8; ++q)
            cp16(rbase + (d * 8 + q) * 2048, &lp4[(d * 8 + q) * 128 + tid]);
        CP_COMMIT();
    }

    float r0 = NEGF, r1 = NEGF, r2 = NEGF, r3 = NEGF;
    unsigned nib = 0;

    for (int c = 0; c < TY / CHUNK; ++c) {
        if (w > 0) asm volatile("bar.sync %0, 64;" :: "r"(8 + w));
#pragma unroll
        for (int g = 0; g < 2; ++g) {
            int y0 = c * CHUNK + g * 8;
            CP_WAIT(1);
            float4 cc[8];
#pragma unroll
            for (int q = 0; q < 8; ++q)
                cc[q] = ring[((y0 + q) & (RINGC - 1)) * 128 + tid];
            float ccL[4];
#pragma unroll
            for (int p = 0; p < 4; ++p)
                ccL[p] = ring[((y0 + 2 * p) & (RINGC - 1)) * 128 + tprev].w;
            float pb[8];
#pragma unroll
            for (int q = 0; q < 8; ++q) {
                int yi = y0 + q - 1;
                pb[q] = (w > 0 && yi >= 0) ? pbnd[yi & 63] : NEGF;
            }
            if (y0 + RINGC < TY) {
#pragma unroll
                for (int q = 0; q < 8; ++q)
                    cp16(rbase + ((y0 + q) & (RINGC - 1)) * 2048,
                         &lp4[(size_t)(y0 + RINGC + q) * 128 + tid]);
            }
            CP_COMMIT();
#pragma unroll
            for (int p = 0; p < 4; ++p) {
                int y = y0 + 2 * p;
                float4 ca = cc[2 * p], cb = cc[2 * p + 1];
                if (y == 0) {
                    // col 0 init
                    float n0 = (gx0 == 0) ? ca.x : NEGF;
                    float n1 = NEGF, n2 = NEGF, n3 = NEGF;
                    // col 1 (left neighbor of col 0 is NEGF everywhere)
                    bool b3 = n2 > n3; r3 = cb.w + fmaxf(n3, n2);
                    bool b2 = n1 > n2; r2 = cb.z + fmaxf(n2, n1);
                    bool b1 = n0 > n1; r1 = cb.y + fmaxf(n1, n0);
                    bool b0 = false;   r0 = cb.x + fmaxf(n0, NEGF);
                    unsigned nbB = (b0 ? 1u : 0u) | (b1 ? 2u : 0u) | (b2 ? 4u : 0u) | (b3 ? 8u : 0u);
                    nib = nbB;                                  // pos 0
                    if (lane == 31) *(float2*)&mybnd[0] = make_float2(n3, r3);
                } else {
                    float s3 = __shfl_up_sync(0xffffffffu, r3, 1);   // issued first
                    float s2 = __shfl_up_sync(0xffffffffu, r2, 1);
                    // col y from V[:, y-1]
                    bool a3 = r2 > r3; float n3 = ca.w + fmaxf(r3, r2);
                    bool a2 = r1 > r2; float n2 = ca.z + fmaxf(r2, r1);
                    bool a1 = r0 > r1; float n1 = ca.y + fmaxf(r1, r0);
                    float La = (lane == 0) ? pb[2 * p] : s3;
                    bool a0 = La > r0; float n0 = ca.x + fmaxf(r0, La);
                    // left neighbor of col y (computed locally from shfl'd pre-update values)
                    float LbN = ccL[p] + fmaxf(s3, s2);
                    float Lb = (lane == 0) ? pb[2 * p + 1] : LbN;
                    // col y+1 from V[:, y]
                    bool b3 = n2 > n3; r3 = cb.w + fmaxf(n3, n2);
                    bool b2 = n1 > n2; r2 = cb.z + fmaxf(n2, n1);
                    bool b1 = n0 > n1; r1 = cb.y + fmaxf(n1, n0);
                    bool b0 = Lb > n0; r0 = cb.x + fmaxf(n0, Lb);
                    unsigned nbA = (a0 ? 1u : 0u) | (a1 ? 2u : 0u) | (a2 ? 4u : 0u) | (a3 ? 8u : 0u);
                    unsigned nbB = (b0 ? 1u : 0u) | (b1 ? 2u : 0u) | (b2 ? 4u : 0u) | (b3 ? 8u : 0u);
                    if (p == 0) {
                        nib |= nbA << 28;                       // pos 7 of previous word
                        sd[((y - 1) >> 3) * 128 + tid] = nib;
                        nib = nbB;                              // pos 0
                    } else {
                        nib |= (nbA << ((2 * p - 1) * 4)) | (nbB << ((2 * p) * 4));
                    }
                    if (lane == 31) *(float2*)&mybnd[y & 63] = make_float2(n3, r3);
                }
            }
        }
        if (w < DPW - 1) asm volatile("bar.sync %0, 64;" :: "r"(9 + w));
    }
    // final partial word (decisions for y-1 = 2040..2046)
    sd[(TY / 8 - 1) * 128 + tid] = nib;
    __syncthreads();

    int txL = xlen[b], tyL = ylen[b];
    if (tid == 0) {
        int idx = txL - 1;
        int y = tyL - 1;
        unsigned wcur = sd[(((y - 1) >= 0 ? (y - 1) : 0) >> 3) * 128 + (idx >> 2)];
        for (; y >= 0; --y) {
            sxs[y] = idx;
            int mv = 0;
            if (idx > 0) {
                if (idx == y) mv = 1;
                else mv = (wcur >> (((y - 1) & 7) * 4 + (idx & 3))) & 1;
            }
            idx -= mv;
            int yn = (y - 2) >= 0 ? (y - 2) : 0;
            wcur = sd[(yn >> 3) * 128 + (idx >> 2)];                 // prefetch next step's word
        }
    }
    __syncthreads();
    // publish xs
    for (int y = tid; y < tyL; y += 128) g_xs[b * TY + y] = sxs[y];
    for (int y = tyL + tid; y < TY; y += 128) g_xs[b * TY + y] = -1;
    // durations via binary search over monotone sxs[0..tyL)
#pragma unroll
    for (int h = 0; h < 4; ++h) {
        int x = h * 128 + tid;
        float dv = 0.0f;
        if (x < txL) {
            int lo = 0, hi = tyL;
            while (lo < hi) { int mid = (lo + hi) >> 1; if (sxs[mid] < x) lo = mid + 1; else hi = mid; }
            int start = lo;
            hi = tyL;
            while (lo < hi) { int mid = (lo + hi) >> 1; if (sxs[mid] < x + 1) lo = mid + 1; else hi = mid; }
            dv = log1pf((float)(lo - start));
        }
        out[OFF_DUR + b * TX + x] = dv;
    }
}

// ---------------- kernel 5: gathers + attn ones ----------------
__global__ void __launch_bounds__(256) gather_kernel(float* __restrict__ out) {
    int t = blockIdx.x * 256 + threadIdx.x;
    if (t >= BB * TY * 20) return;
    int bs = t / 20;
    int c4 = (t % 20) * 4;
    int b  = bs >> 11;
    int xs = g_xs[bs];
    float4 m = make_float4(0.f, 0.f, 0.f, 0.f), l = m;
    if (xs >= 0) {
        size_t rb = ((size_t)b * TX + xs) * CC + c4;
        m = *(const float4*)&g_omT[rb];
        l = *(const float4*)&g_olsT[rb];
        if (c4 == 0) out[OFF_AT + (size_t)bs * TX + xs] = 1.0f;
    }
    *(float4*)&out[OFF_M + (size_t)bs * CC + c4] = m;
    *(float4*)&out[OFF_L + (size_t)bs * CC + c4] = l;
}

// ---------------- launch ----------------
extern "C" void kernel_launch(void* const* d_in, const int* in_sizes, int n_in,
                              void* d_out, int out_size) {
    const float* om   = (const float*)d_in[0];
    const float* ols  = (const float*)d_in[1];
    const float* z    = (const float*)d_in[2];
    const int*   xlen = (const int*)d_in[3];
    const int*   ylen = (const int*)d_in[4];
    float* out = (float*)d_out;

    static bool attr_set = false;
    if (!attr_set) {
        cudaFuncSetAttribute(fwd_kernel, cudaFuncAttributeMaxDynamicSharedMemorySize, FWD_SMEM);
        cudaFuncSetAttribute(gemm_logp, cudaFuncAttributeMaxDynamicSharedMemorySize, GEMM_SMEM);
        attr_set = true;
    }

    prep_kernel<<<dim3(TX / 128, BB), 128>>>(om, ols);
    pre_out<<<496, 512>>>(z, om, ols, ylen, out);
    gemm_logp<<<dim3(TX / 128, TY / 128, BB), 256, GEMM_SMEM>>>(z, xlen, ylen);
    fwd_kernel<<<BB, DPW * 32, FWD_SMEM>>>(xlen, ylen, out);
    gather_kernel<<<(BB * TY * 20 + 255) / 256, 256>>>(out);
}

// round 13
// speedup vs baseline: 1.1462x; 1.1462x over previous
#include <cuda_runtime.h>
#include <cstdint>

#define BB 16
#define CC 80
#define TX 512
#define TY 2048
#define NEGF (-1000000000.0f)

// Output layout (flat concat, fp32):
// z_T [B,TY,C], y_mean_T [B,TY,C], y_ls_T [B,TY,C], attn_T [B,TY,TX], dur [B,TX,1]
#define N_ZT   ((size_t)BB * TY * CC)
#define OFF_Z   ((size_t)0)
#define OFF_M   (N_ZT)
#define OFF_L   (2 * N_ZT)
#define OFF_AT  (3 * N_ZT)
#define OFF_DUR (3 * N_ZT + (size_t)BB * TY * TX)

// ---------------- scratch ----------------
__device__ float g_a   [BB * CC * TX];
__device__ float g_ms  [BB * CC * TX];
__device__ float g_bias[BB * TX];
__device__ float g_logp[(size_t)BB * TY * TX];
__device__ int   g_xs  [BB * TY];
__device__ float g_omT [BB * TX * CC];   // [b][x][c]
__device__ float g_olsT[BB * TX * CC];
__device__ int   g_done[BB * 16];        // per-(batch, ytile) x-tile completion count

// ---------------- f32x2 helpers ----------------
__device__ __forceinline__ unsigned long long pack2(float lo, float hi) {
    unsigned long long r;
    asm("mov.b64 %0, {%1, %2};" : "=l"(r) : "f"(lo), "f"(hi));
    return r;
}
__device__ __forceinline__ float2 unpack2(unsigned long long v) {
    float lo, hi;
    asm("mov.b64 {%0, %1}, %2;" : "=f"(lo), "=f"(hi) : "l"(v));
    return make_float2(lo, hi);
}
__device__ __forceinline__ unsigned long long fma2(unsigned long long a,
                                                   unsigned long long b,
                                                   unsigned long long c) {
    unsigned long long d;
    asm("fma.rn.f32x2 %0, %1, %2, %3;" : "=l"(d) : "l"(a), "l"(b), "l"(c));
    return d;
}
__device__ __forceinline__ unsigned swz(unsigned b) {
    return b ^ ((b >> 3) & 0x70u);
}
__device__ __forceinline__ void cp16cg(unsigned smem_addr, const void* gptr) {
    asm volatile("cp.async.cg.shared.global [%0], [%1], 16;\n"
                 :: "r"(smem_addr), "l"(gptr));
}
#define CP_COMMIT() asm volatile("cp.async.commit_group;\n" ::: "memory")
#define CP_WAIT(n)  asm volatile("cp.async.wait_group %0;\n" :: "n"(n) : "memory")

// acquire-spin until ytile t of batch b has all 4 x-tiles done
__device__ __forceinline__ void wait_tile(int b, int t, int& t_seen) {
    if (t <= t_seen) return;
    volatile int* p = &g_done[b * 16 + t];
    while (*p < 4) __nanosleep(200);
    __threadfence();
    t_seen = t;
}

// ---------------- kernel 1: prep (+ zero done counters) ----------------
__global__ void __launch_bounds__(128) prep_kernel(const float* __restrict__ om,
                                                   const float* __restrict__ ols) {
    int b = blockIdx.y;
    int x = blockIdx.x * 128 + threadIdx.x;
    if (blockIdx.x == 0 && blockIdx.y == 0 && threadIdx.x < 128) {
        g_done[threadIdx.x] = 0;
        g_done[threadIdx.x + 128] = 0;
    }
    float acc = 0.0f;
    for (int c = 0; c < CC; ++c) {
        size_t i = ((size_t)b * CC + c) * TX + x;
        float ls = ols[i];
        float m  = om[i];
        float a  = expf(-2.0f * ls);
        g_a[i]  = a;
        g_ms[i] = m * a;
        acc += -0.9189385332046727f - ls - 0.5f * m * m * a;
    }
    g_bias[b * TX + x] = acc;
}

// ---------------- kernel 2: pre_out (transposes + attn zero-fill) ----------------
#define NFILL 112
__global__ void __launch_bounds__(512) pre_out(const float* __restrict__ z,
                                               const float* __restrict__ om,
                                               const float* __restrict__ ols,
                                               const int* __restrict__ ylen,
                                               float* __restrict__ out) {
    __shared__ float tile[CC * 129];
    int bid = blockIdx.x;
    int tid = threadIdx.x;
    if (bid < 384) {
        int role, idx;
        const float* src;
        int srcN;
        if (bid < 256)      { role = 0; idx = bid;       src = z;   srcN = TY; }
        else if (bid < 320) { role = 1; idx = bid - 256; src = om;  srcN = TX; }
        else                { role = 2; idx = bid - 320; src = ols; srcN = TX; }
        int tilesPerB = (role == 0) ? 16 : 4;
        int b  = idx / tilesPerB;
        int n0 = (idx % tilesPerB) * 128;
        int tyL = ylen[b];
#pragma unroll
        for (int i = 0; i < 5; ++i) {
            int f  = tid + i * 512;
            int c  = f >> 5;
            int s4 = (f & 31) << 2;
            float4 v = *(const float4*)&src[((size_t)b * CC + c) * srcN + n0 + s4];
            int base = c * 129 + s4;
            tile[base]     = v.x;
            tile[base + 1] = v.y;
            tile[base + 2] = v.z;
            tile[base + 3] = v.w;
        }
        __syncthreads();
#pragma unroll
        for (int i = 0; i < 5; ++i) {
            int f  = tid + i * 512;
            int sl = f / 20;
            int c4 = (f % 20) * 4;
            float4 o;
            o.x = tile[(c4 + 0) * 129 + sl];
            o.y = tile[(c4 + 1) * 129 + sl];
            o.z = tile[(c4 + 2) * 129 + sl];
            o.w = tile[(c4 + 3) * 129 + sl];
            int n = n0 + sl;
            if (role == 0) {
                if (n >= tyL) o = make_float4(0.f, 0.f, 0.f, 0.f);
                *(float4*)&out[OFF_Z + ((size_t)b * TY + n) * CC + c4] = o;
            } else {
                float* dst = (role == 1) ? g_omT : g_olsT;
                *(float4*)&dst[((size_t)b * TX + n) * CC + c4] = o;
            }
        }
    } else {
        size_t total = (size_t)BB * TY * TX / 4;
        float4* p = (float4*)&out[OFF_AT];
        float4 zv = make_float4(0.f, 0.f, 0.f, 0.f);
        size_t start = (size_t)(bid - 384) * 512 + tid;
        for (size_t i = start; i < total; i += (size_t)NFILL * 512)
            p[i] = zv;
    }
}

// ---------------- kernel 3: MEGA (gemm blocks + fwd DP blocks, overlapped) ----------------
// fwd smem layout: sd[TY/8][128] u32 128KB | bndw[4][64] 1KB | sxs[TY] 8KB | ring[16][128] f4 32KB
// gemm smem layout: A 16K | M 16K | Z1 8K | Z2 8K   (both fit in the uniform dynamic buffer)
#define DPW 4
#define CHUNK 16
#define RINGC 16
#define SD_WORDS (TY / 8 * 128)
#define MEGA_SMEM (SD_WORDS * 4 + DPW * 64 * 4 + TY * 4 + RINGC * 128 * 16)

__global__ void __launch_bounds__(256, 1) mega_kernel(const float* __restrict__ z,
                                                      const int* __restrict__ xlen,
                                                      const int* __restrict__ ylen,
                                                      float* __restrict__ out) {
    extern __shared__ __align__(16) unsigned char msm[];
    int bid = blockIdx.x;
    int tid = threadIdx.x;

    if (bid < 16) {
        // ================= fwd DP role (threads 0..127 active in DP) =================
        unsigned* sd = (unsigned*)msm;                                     // [TY/8][128]
        float* bndw = (float*)(msm + (size_t)SD_WORDS * 4);                // [DPW][64]
        int* sxs = (int*)(msm + (size_t)SD_WORDS * 4 + DPW * 64 * 4);      // [TY]
        float4* ring = (float4*)(msm + (size_t)SD_WORDS * 4 + DPW * 64 * 4 + TY * 4);

        int b = bid;
        int w = tid >> 5, lane = tid & 31;
        const float4* lp4 = (const float4*)&g_logp[(size_t)b * TY * TX];
        int gx0 = tid * 4;
        float* mybnd = bndw + w * 64;
        const float* pbnd = bndw + (w - 1) * 64;
        bool dp = (tid < 128);

        if (dp) {
            unsigned rbase = (unsigned)__cvta_generic_to_shared(ring) + tid * 16;
            int t_seen = -1;
            wait_tile(b, 0, t_seen);
            // prime: 2 groups of 8 columns
#pragma unroll
            for (int d = 0; d < 2; ++d) {
#pragma unroll
                for (int q = 0; q < 8; ++q)
                    cp16cg(rbase + (d * 8 + q) * 2048, &lp4[(d * 8 + q) * 128 + tid]);
                CP_COMMIT();
            }

            float r0 = NEGF, r1 = NEGF, r2 = NEGF, r3 = NEGF;
            unsigned nib = 0;

            for (int c = 0; c < TY / CHUNK; ++c) {
                int t_need = (c * CHUNK + 31) >> 7;
                if (t_need > 15) t_need = 15;
                wait_tile(b, t_need, t_seen);
                if (w > 0) asm volatile("bar.sync %0, 64;" :: "r"(8 + w));
#pragma unroll
                for (int g = 0; g < 2; ++g) {
                    int y0 = c * CHUNK + g * 8;
                    CP_WAIT(1);
                    float4 cc[8];
#pragma unroll
                    for (int q = 0; q < 8; ++q)
                        cc[q] = ring[((y0 + q) & (RINGC - 1)) * 128 + tid];
                    float pb[8];
#pragma unroll
                    for (int q = 0; q < 8; ++q) {
                        int yi = y0 + q - 1;
                        pb[q] = (w > 0 && yi >= 0) ? pbnd[yi & 63] : NEGF;
                    }
                    if (y0 + RINGC < TY) {
#pragma unroll
                        for (int q = 0; q < 8; ++q)
                            cp16cg(rbase + ((y0 + q) & (RINGC - 1)) * 2048,
                                   &lp4[(size_t)(y0 + RINGC + q) * 128 + tid]);
                    }
                    CP_COMMIT();
#pragma unroll
                    for (int j = 0; j < 8; ++j) {
                        int y = y0 + j;
                        if (y == 0) {
                            r0 = (gx0 == 0) ? cc[0].x : NEGF;
                            r1 = r2 = r3 = NEGF;
                            if (lane == 31) mybnd[0] = r3;
                        } else {
                            float ls = __shfl_up_sync(0xffffffffu, r3, 1);   // issued first
                            bool c3 = r2 > r3; r3 = cc[j].w + fmaxf(r3, r2);
                            bool c2 = r1 > r2; r2 = cc[j].z + fmaxf(r2, r1);
                            bool c1 = r0 > r1; r1 = cc[j].y + fmaxf(r1, r0);
                            float left = (lane == 0) ? pb[j] : ls;           // consume late
                            bool c0 = left > r0;
                            r0 = cc[j].x + fmaxf(r0, left);
                            unsigned nb = (c0 ? 1u : 0u) | (c1 ? 2u : 0u) |
                                          (c2 ? 4u : 0u) | (c3 ? 8u : 0u);
                            if (j == 0 && g == 0) {
                                nib |= nb << 28;
                                sd[(c * 2 - 1) * 128 + tid] = nib;
                                nib = 0;
                            } else if (j == 0) {
                                nib |= nb << 28;
                                sd[(c * 2) * 128 + tid] = nib;
                                nib = 0;
                            } else {
                                nib |= nb << ((j - 1) * 4);
                            }
                            if (lane == 31) mybnd[y & 63] = r3;
                        }
                    }
                }
                if (w < DPW - 1) asm volatile("bar.sync %0, 64;" :: "r"(9 + w));
            }
            // final partial word (decisions for y-1 = 2040..2046)
            sd[(TY / 8 - 1) * 128 + tid] = nib;
        }
        __syncthreads();

        int txL = xlen[b], tyL = ylen[b];
        if (tid == 0) {
            int idx = txL - 1;
            int y = tyL - 1;
            unsigned wcur = sd[(((y - 1) >= 0 ? (y - 1) : 0) >> 3) * 128 + (idx >> 2)];
            for (; y >= 0; --y) {
                sxs[y] = idx;
                int mv = 0;
                if (idx > 0) {
                    if (idx == y) mv = 1;
                    else mv = (wcur >> (((y - 1) & 7) * 4 + (idx & 3))) & 1;
                }
                idx -= mv;
                int yn = (y - 2) >= 0 ? (y - 2) : 0;
                wcur = sd[(yn >> 3) * 128 + (idx >> 2)];   // prefetch next step's word
            }
        }
        __syncthreads();
        // publish xs (256 threads)
        for (int y = tid; y < tyL; y += 256) g_xs[b * TY + y] = sxs[y];
        for (int y = tyL + tid; y < TY; y += 256) g_xs[b * TY + y] = -1;
        // durations via binary search over monotone sxs[0..tyL)
#pragma unroll
        for (int h = 0; h < 2; ++h) {
            int x = h * 256 + tid;
            float dv = 0.0f;
            if (x < txL) {
                int lo = 0, hi = tyL;
                while (lo < hi) { int mid = (lo + hi) >> 1; if (sxs[mid] < x) lo = mid + 1; else hi = mid; }
                int start = lo;
                hi = tyL;
                while (lo < hi) { int mid = (lo + hi) >> 1; if (sxs[mid] < x + 1) lo = mid + 1; else hi = mid; }
                dv = log1pf((float)(lo - start));
            }
            out[OFF_DUR + b * TX + x] = dv;
        }
    } else {
        // ================= gemm role (ytile-outermost ordering) =================
        unsigned char* smA  = msm;
        unsigned char* smM  = msm + 16384;
        unsigned char* smZ1 = msm + 32768;
        unsigned char* smZ2 = msm + 40960;

        int bid2 = bid - 16;
        int ty = bid2 >> 6;            // 0..15  (all batches' ytile 0 first)
        int b  = (bid2 >> 2) & 15;
        int x0 = (bid2 & 3) * 128;
        int y0 = ty * 128;
        int txi = tid & 15;
        int tyi = tid >> 4;
        int xl = txi * 8;
        int yl = tyi * 8;

        unsigned aoff[4];
#pragma unroll
        for (int g = 0; g < 4; ++g) aoff[g] = swz((unsigned)(txi * 64 + g * 16));
        unsigned zoff = (unsigned)(tyi * 32);

        unsigned long long acc[8][4];
#pragma unroll
        for (int i = 0; i < 8; ++i)
#pragma unroll
            for (int j = 0; j < 4; ++j) acc[i][j] = 0ULL;

        for (int kc = 0; kc < CC; kc += 16) {
            __syncthreads();
#pragma unroll
            for (int i = 0; i < 2; ++i) {
                int f  = tid + i * 256;
                int r  = f >> 5;
                int c4 = (f & 31) << 2;
                size_t gi = ((size_t)b * CC + kc + r) * TX + x0 + c4;
                float4 av = *(const float4*)&g_a[gi];
                float4 mv = *(const float4*)&g_ms[gi];
                unsigned sb0 = swz((unsigned)(c4 * 8));
                unsigned sb1 = swz((unsigned)(c4 * 8 + 16));
                *(ulonglong2*)(smA + r * 1024 + sb0) = make_ulonglong2(pack2(av.x, av.x), pack2(av.y, av.y));
                *(ulonglong2*)(smA + r * 1024 + sb1) = make_ulonglong2(pack2(av.z, av.z), pack2(av.w, av.w));
                *(ulonglong2*)(smM + r * 1024 + sb0) = make_ulonglong2(pack2(mv.x, mv.x), pack2(mv.y, mv.y));
                *(ulonglong2*)(smM + r * 1024 + sb1) = make_ulonglong2(pack2(mv.z, mv.z), pack2(mv.w, mv.w));
            }
#pragma unroll
            for (int i = 0; i < 2; ++i) {
                int f  = tid + i * 256;
                int r  = f >> 5;
                int c4 = (f & 31) << 2;
                size_t gi = ((size_t)b * CC + kc + r) * TY + y0 + c4;
                float4 zv = *(const float4*)&z[gi];
                ulonglong2* p1 = (ulonglong2*)(smZ1 + r * 512 + (f & 31) * 16);
                ulonglong2* p2 = (ulonglong2*)(smZ2 + r * 512 + (f & 31) * 16);
                *p1 = make_ulonglong2(pack2(zv.x, zv.y), pack2(zv.z, zv.w));
                *p2 = make_ulonglong2(pack2(-0.5f * zv.x * zv.x, -0.5f * zv.y * zv.y),
                                      pack2(-0.5f * zv.z * zv.z, -0.5f * zv.w * zv.w));
            }
            __syncthreads();
#pragma unroll
            for (int k = 0; k < 16; ++k) {
                const unsigned char* rowA = smA + k * 1024;
                const unsigned char* rowM = smM + k * 1024;
                ulonglong2 z1a = *(const ulonglong2*)(smZ1 + k * 512 + zoff);
                ulonglong2 z1b = *(const ulonglong2*)(smZ1 + k * 512 + zoff + 16);
                ulonglong2 z2a = *(const ulonglong2*)(smZ2 + k * 512 + zoff);
                ulonglong2 z2b = *(const ulonglong2*)(smZ2 + k * 512 + zoff + 16);
                unsigned long long z1p[4] = {z1a.x, z1a.y, z1b.x, z1b.y};
                unsigned long long z2p[4] = {z2a.x, z2a.y, z2b.x, z2b.y};
#pragma unroll
                for (int g = 0; g < 4; ++g) {
                    ulonglong2 a2 = *(const ulonglong2*)(rowA + aoff[g]);
                    ulonglong2 m2 = *(const ulonglong2*)(rowM + aoff[g]);
#pragma unroll
                    for (int yp = 0; yp < 4; ++yp) {
                        acc[2 * g][yp]     = fma2(a2.x, z2p[yp], acc[2 * g][yp]);
                        acc[2 * g][yp]     = fma2(m2.x, z1p[yp], acc[2 * g][yp]);
                        acc[2 * g + 1][yp] = fma2(a2.y, z2p[yp], acc[2 * g + 1][yp]);
                        acc[2 * g + 1][yp] = fma2(m2.y, z1p[yp], acc[2 * g + 1][yp]);
                    }
                }
            }
        }

        int txL = xlen[b], tyL = ylen[b];
        float bv[8];
        *(float4*)&bv[0] = *(const float4*)&g_bias[b * TX + x0 + xl];
        *(float4*)&bv[4] = *(const float4*)&g_bias[b * TX + x0 + xl + 4];
#pragma unroll
        for (int yy = 0; yy < 8; ++yy) {
            int y = y0 + yl + yy;
            bool yok = (y < tyL);
            int yp = yy >> 1;
            bool hi = (yy & 1);
            float o[8];
#pragma unroll
            for (int j = 0; j < 8; ++j) {
                float2 u = unpack2(acc[j][yp]);
                float v = hi ? u.y : u.x;
                int x = x0 + xl + j;
                o[j] = (yok && x < txL) ? (bv[j] + v) : 0.0f;
            }
            size_t base = ((size_t)b * TY + y) * TX + x0 + xl;
            *(float4*)&g_logp[base]     = make_float4(o[0], o[1], o[2], o[3]);
            *(float4*)&g_logp[base + 4] = make_float4(o[4], o[5], o[6], o[7]);
        }
        // release: make this tile visible, then count it
        __threadfence();
        __syncthreads();
        if (tid == 0) atomicAdd(&g_done[b * 16 + ty], 1);
    }
}

// ---------------- kernel 5: gathers + attn ones ----------------
__global__ void __launch_bounds__(256) gather_kernel(float* __restrict__ out) {
    int t = blockIdx.x * 256 + threadIdx.x;
    if (t >= BB * TY * 20) return;
    int bs = t / 20;
    int c4 = (t % 20) * 4;
    int b  = bs >> 11;
    int xs = g_xs[bs];
    float4 m = make_float4(0.f, 0.f, 0.f, 0.f), l = m;
    if (xs >= 0) {
        size_t rb = ((size_t)b * TX + xs) * CC + c4;
        m = *(const float4*)&g_omT[rb];
        l = *(const float4*)&g_olsT[rb];
        if (c4 == 0) out[OFF_AT + (size_t)bs * TX + xs] = 1.0f;
    }
    *(float4*)&out[OFF_M + (size_t)bs * CC + c4] = m;
    *(float4*)&out[OFF_L + (size_t)bs * CC + c4] = l;
}

// ---------------- launch ----------------
extern "C" void kernel_launch(void* const* d_in, const int* in_sizes, int n_in,
                              void* d_out, int out_size) {
    const float* om   = (const float*)d_in[0];
    const float* ols  = (const float*)d_in[1];
    const float* z    = (const float*)d_in[2];
    const int*   xlen = (const int*)d_in[3];
    const int*   ylen = (const int*)d_in[4];
    float* out = (float*)d_out;

    static bool attr_set = false;
    if (!attr_set) {
        cudaFuncSetAttribute(mega_kernel, cudaFuncAttributeMaxDynamicSharedMemorySize, MEGA_SMEM);
        attr_set = true;
    }

    prep_kernel<<<dim3(TX / 128, BB), 128>>>(om, ols);
    mega_kernel<<<16 + 1024, 256, MEGA_SMEM>>>(z, xlen, ylen, out);
    pre_out<<<496, 512>>>(z, om, ols, ylen, out);
    gather_kernel<<<(BB * TY * 20 + 255) / 256, 256>>>(out);
}

// round 14
// speedup vs baseline: 1.2576x; 1.0971x over previous
#include <cuda_runtime.h>
#include <cstdint>

#define BB 16
#define CC 80
#define TX 512
#define TY 2048
#define NEGF (-1000000000.0f)

// Output layout (flat concat, fp32):
// z_T [B,TY,C], y_mean_T [B,TY,C], y_ls_T [B,TY,C], attn_T [B,TY,TX], dur [B,TX,1]
#define N_ZT   ((size_t)BB * TY * CC)
#define OFF_Z   ((size_t)0)
#define OFF_M   (N_ZT)
#define OFF_L   (2 * N_ZT)
#define OFF_AT  (3 * N_ZT)
#define OFF_DUR (3 * N_ZT + (size_t)BB * TY * TX)

// ---------------- scratch ----------------
__device__ float g_a   [BB * CC * TX];
__device__ float g_ms  [BB * CC * TX];
__device__ float g_bias[BB * TX];
__device__ float g_logp[(size_t)BB * TY * TX];
__device__ int   g_xs  [BB * TY];
__device__ float g_omT [BB * TX * CC];   // [b][x][c]
__device__ float g_olsT[BB * TX * CC];
__device__ int   g_done[BB * 8];         // per-(batch, 256-row ytile-pair) x-tile completion

// ---------------- f32x2 helpers ----------------
__device__ __forceinline__ unsigned long long pack2(float lo, float hi) {
    unsigned long long r;
    asm("mov.b64 %0, {%1, %2};" : "=l"(r) : "f"(lo), "f"(hi));
    return r;
}
__device__ __forceinline__ float2 unpack2(unsigned long long v) {
    float lo, hi;
    asm("mov.b64 {%0, %1}, %2;" : "=f"(lo), "=f"(hi) : "l"(v));
    return make_float2(lo, hi);
}
__device__ __forceinline__ unsigned long long fma2(unsigned long long a,
                                                   unsigned long long b,
                                                   unsigned long long c) {
    unsigned long long d;
    asm("fma.rn.f32x2 %0, %1, %2, %3;" : "=l"(d) : "l"(a), "l"(b), "l"(c));
    return d;
}
__device__ __forceinline__ unsigned swz(unsigned b) {
    return b ^ ((b >> 3) & 0x70u);
}
__device__ __forceinline__ void cp16cg(unsigned smem_addr, const void* gptr) {
    asm volatile("cp.async.cg.shared.global [%0], [%1], 16;\n"
                 :: "r"(smem_addr), "l"(gptr));
}
#define CP_COMMIT() asm volatile("cp.async.commit_group;\n" ::: "memory")
#define CP_WAIT(n)  asm volatile("cp.async.wait_group %0;\n" :: "n"(n) : "memory")

// acquire-spin until 256-row ytile-pair tp of batch b has all 4 x-tiles done
__device__ __forceinline__ void wait_pair(int b, int tp, int& tp_seen) {
    if (tp <= tp_seen) return;
    volatile int* p = &g_done[b * 8 + tp];
    while (*p < 4) __nanosleep(200);
    __threadfence();
    tp_seen = tp;
}

// ---------------- kernel 1: prep (+ zero done counters) ----------------
__global__ void __launch_bounds__(128) prep_kernel(const float* __restrict__ om,
                                                   const float* __restrict__ ols) {
    int b = blockIdx.y;
    int x = blockIdx.x * 128 + threadIdx.x;
    if (blockIdx.x == 0 && blockIdx.y == 0 && threadIdx.x < 128)
        g_done[threadIdx.x] = 0;
    float acc = 0.0f;
    for (int c = 0; c < CC; ++c) {
        size_t i = ((size_t)b * CC + c) * TX + x;
        float ls = ols[i];
        float m  = om[i];
        float a  = expf(-2.0f * ls);
        g_a[i]  = a;
        g_ms[i] = m * a;
        acc += -0.9189385332046727f - ls - 0.5f * m * m * a;
    }
    g_bias[b * TX + x] = acc;
}

// ---------------- kernel 2: MEGA (DP blocks + gemm blocks + pre_out blocks) ----------------
// DP smem: sd[TY/8][128] u32 128KB | bndw[4][64] 1KB | sxs[TY] 8KB | ring[16][128] f4 32KB
// gemm smem: A 16K | M 16K | Z1 16K | Z2 16K (64KB)
// pre_out smem: tile[80*129] f32 (~41KB)
#define DPW 4
#define CHUNK 16
#define RINGC 16
#define SD_WORDS (TY / 8 * 128)
#define MEGA_SMEM (SD_WORDS * 4 + DPW * 64 * 4 + TY * 4 + RINGC * 128 * 16)
#define NFILL 112
#define GEMM_BLKS 512                     // 8 typairs x 16 b x 4 xtiles
#define PRE_BLKS 496

__global__ void __launch_bounds__(512, 1) mega_kernel(const float* __restrict__ z,
                                                      const float* __restrict__ om,
                                                      const float* __restrict__ ols,
                                                      const int* __restrict__ xlen,
                                                      const int* __restrict__ ylen,
                                                      float* __restrict__ out) {
    extern __shared__ __align__(16) unsigned char msm[];
    int bid = blockIdx.x;
    int tid = threadIdx.x;

    if (bid < 16) {
        // ================= DP role (threads 0..127 run the systolic loop) =================
        unsigned* sd = (unsigned*)msm;                                     // [TY/8][128]
        float* bndw = (float*)(msm + (size_t)SD_WORDS * 4);                // [DPW][64]
        int* sxs = (int*)(msm + (size_t)SD_WORDS * 4 + DPW * 64 * 4);      // [TY]
        float4* ring = (float4*)(msm + (size_t)SD_WORDS * 4 + DPW * 64 * 4 + TY * 4);

        int b = bid;
        int w = tid >> 5, lane = tid & 31;
        const float4* lp4 = (const float4*)&g_logp[(size_t)b * TY * TX];
        int gx0 = tid * 4;
        float* mybnd = bndw + w * 64;
        const float* pbnd = bndw + (w - 1) * 64;

        if (tid < 128) {
            unsigned rbase = (unsigned)__cvta_generic_to_shared(ring) + tid * 16;
            int tp_seen = -1;
            wait_pair(b, 0, tp_seen);
            // prime: 2 groups of 8 columns
#pragma unroll
            for (int d = 0; d < 2; ++d) {
#pragma unroll
                for (int q = 0; q < 8; ++q)
                    cp16cg(rbase + (d * 8 + q) * 2048, &lp4[(d * 8 + q) * 128 + tid]);
                CP_COMMIT();
            }

            float r0 = NEGF, r1 = NEGF, r2 = NEGF, r3 = NEGF;
            unsigned nib = 0;

            for (int c = 0; c < TY / CHUNK; ++c) {
                int tp_need = (c * CHUNK + 31) >> 8;
                if (tp_need > 7) tp_need = 7;
                wait_pair(b, tp_need, tp_seen);
                if (w > 0) asm volatile("bar.sync %0, 64;" :: "r"(8 + w));
#pragma unroll
                for (int g = 0; g < 2; ++g) {
                    int y0 = c * CHUNK + g * 8;
                    CP_WAIT(1);
                    float4 cc[8];
#pragma unroll
                    for (int q = 0; q < 8; ++q)
                        cc[q] = ring[((y0 + q) & (RINGC - 1)) * 128 + tid];
                    float pb[8];
#pragma unroll
                    for (int q = 0; q < 8; ++q) {
                        int yi = y0 + q - 1;
                        pb[q] = (w > 0 && yi >= 0) ? pbnd[yi & 63] : NEGF;
                    }
                    if (y0 + RINGC < TY) {
#pragma unroll
                        for (int q = 0; q < 8; ++q)
                            cp16cg(rbase + ((y0 + q) & (RINGC - 1)) * 2048,
                                   &lp4[(size_t)(y0 + RINGC + q) * 128 + tid]);
                    }
                    CP_COMMIT();
#pragma unroll
                    for (int j = 0; j < 8; ++j) {
                        int y = y0 + j;
                        if (y == 0) {
                            r0 = (gx0 == 0) ? cc[0].x : NEGF;
                            r1 = r2 = r3 = NEGF;
                            if (lane == 31) mybnd[0] = r3;
                        } else {
                            float ls = __shfl_up_sync(0xffffffffu, r3, 1);   // issued first
                            bool c3 = r2 > r3; r3 = cc[j].w + fmaxf(r3, r2);
                            bool c2 = r1 > r2; r2 = cc[j].z + fmaxf(r2, r1);
                            bool c1 = r0 > r1; r1 = cc[j].y + fmaxf(r1, r0);
                            float left = (lane == 0) ? pb[j] : ls;           // consume late
                            bool c0 = left > r0;
                            r0 = cc[j].x + fmaxf(r0, left);
                            unsigned nb = (c0 ? 1u : 0u) | (c1 ? 2u : 0u) |
                                          (c2 ? 4u : 0u) | (c3 ? 8u : 0u);
                            if (j == 0) {
                                nib |= nb << 28;
                                sd[((y - 1) >> 3) * 128 + tid] = nib;
                                nib = 0;
                            } else {
                                nib |= nb << ((j - 1) * 4);
                            }
                            if (lane == 31) mybnd[y & 63] = r3;
                        }
                    }
                }
                if (w < DPW - 1) asm volatile("bar.sync %0, 64;" :: "r"(9 + w));
            }
            // final partial word (decisions for y-1 = 2040..2046)
            sd[(TY / 8 - 1) * 128 + tid] = nib;
        }
        __syncthreads();

        int txL = xlen[b], tyL = ylen[b];
        if (tid == 0) {
            int idx = txL - 1;
            int y = tyL - 1;
            unsigned wcur = sd[(((y - 1) >= 0 ? (y - 1) : 0) >> 3) * 128 + (idx >> 2)];
            for (; y >= 0; --y) {
                sxs[y] = idx;
                int mv = 0;
                if (idx > 0) {
                    if (idx == y) mv = 1;
                    else mv = (wcur >> (((y - 1) & 7) * 4 + (idx & 3))) & 1;
                }
                idx -= mv;
                int yn = (y - 2) >= 0 ? (y - 2) : 0;
                wcur = sd[(yn >> 3) * 128 + (idx >> 2)];   // prefetch next step's word
            }
        }
        __syncthreads();
        // publish xs (512 threads)
        for (int y = tid; y < tyL; y += 512) g_xs[b * TY + y] = sxs[y];
        for (int y = tyL + tid; y < TY; y += 512) g_xs[b * TY + y] = -1;
        // durations via binary search over monotone sxs[0..tyL); one x per thread
        {
            int x = tid;
            float dv = 0.0f;
            if (x < txL) {
                int lo = 0, hi = tyL;
                while (lo < hi) { int mid = (lo + hi) >> 1; if (sxs[mid] < x) lo = mid + 1; else hi = mid; }
                int start = lo;
                hi = tyL;
                while (lo < hi) { int mid = (lo + hi) >> 1; if (sxs[mid] < x + 1) lo = mid + 1; else hi = mid; }
                dv = log1pf((float)(lo - start));
            }
            out[OFF_DUR + b * TX + x] = dv;
        }
    } else if (bid < 16 + GEMM_BLKS) {
        // ================= gemm role (512 thr, 128x x 256y tile, typair-outermost) ==========
        unsigned char* smA  = msm;
        unsigned char* smM  = msm + 16384;
        unsigned char* smZ1 = msm + 32768;
        unsigned char* smZ2 = msm + 49152;

        int bid2 = bid - 16;
        int tp = bid2 >> 6;            // 0..7  (all batches' typair 0 first)
        int b  = (bid2 >> 2) & 15;
        int x0 = (bid2 & 3) * 128;
        int y0 = tp * 256;
        int txi = tid & 15;            // 16 x-groups of 8
        int tyi = tid >> 4;            // 32 y-groups of 8
        int xl = txi * 8;
        int yl = tyi * 8;

        unsigned aoff[4];
#pragma unroll
        for (int g = 0; g < 4; ++g) aoff[g] = swz((unsigned)(txi * 64 + g * 16));
        unsigned zoff = (unsigned)(tyi * 32);

        unsigned long long acc[8][4];
#pragma unroll
        for (int i = 0; i < 8; ++i)
#pragma unroll
            for (int j = 0; j < 4; ++j) acc[i][j] = 0ULL;

        for (int kc = 0; kc < CC; kc += 16) {
            __syncthreads();
            // A/M: 16 rows x 128 x = 512 float4; 1 per thread
            {
                int f  = tid;
                int r  = f >> 5;
                int c4 = (f & 31) << 2;
                size_t gi = ((size_t)b * CC + kc + r) * TX + x0 + c4;
                float4 av = *(const float4*)&g_a[gi];
                float4 mv = *(const float4*)&g_ms[gi];
                unsigned sb0 = swz((unsigned)(c4 * 8));
                unsigned sb1 = swz((unsigned)(c4 * 8 + 16));
                *(ulonglong2*)(smA + r * 1024 + sb0) = make_ulonglong2(pack2(av.x, av.x), pack2(av.y, av.y));
                *(ulonglong2*)(smA + r * 1024 + sb1) = make_ulonglong2(pack2(av.z, av.z), pack2(av.w, av.w));
                *(ulonglong2*)(smM + r * 1024 + sb0) = make_ulonglong2(pack2(mv.x, mv.x), pack2(mv.y, mv.y));
                *(ulonglong2*)(smM + r * 1024 + sb1) = make_ulonglong2(pack2(mv.z, mv.z), pack2(mv.w, mv.w));
            }
            // Z: 16 rows x 256 y = 1024 float4; 2 per thread
#pragma unroll
            for (int i = 0; i < 2; ++i) {
                int f  = tid + i * 512;
                int r  = f >> 6;
                int c4 = (f & 63) << 2;
                size_t gi = ((size_t)b * CC + kc + r) * TY + y0 + c4;
                float4 zv = *(const float4*)&z[gi];
                ulonglong2* p1 = (ulonglong2*)(smZ1 + r * 1024 + (f & 63) * 16);
                ulonglong2* p2 = (ulonglong2*)(smZ2 + r * 1024 + (f & 63) * 16);
                *p1 = make_ulonglong2(pack2(zv.x, zv.y), pack2(zv.z, zv.w));
                *p2 = make_ulonglong2(pack2(-0.5f * zv.x * zv.x, -0.5f * zv.y * zv.y),
                                      pack2(-0.5f * zv.z * zv.z, -0.5f * zv.w * zv.w));
            }
            __syncthreads();
#pragma unroll
            for (int k = 0; k < 16; ++k) {
                const unsigned char* rowA = smA + k * 1024;
                const unsigned char* rowM = smM + k * 1024;
                ulonglong2 z1a = *(const ulonglong2*)(smZ1 + k * 1024 + zoff);
                ulonglong2 z1b = *(const ulonglong2*)(smZ1 + k * 1024 + zoff + 16);
                ulonglong2 z2a = *(const ulonglong2*)(smZ2 + k * 1024 + zoff);
                ulonglong2 z2b = *(const ulonglong2*)(smZ2 + k * 1024 + zoff + 16);
                unsigned long long z1p[4] = {z1a.x, z1a.y, z1b.x, z1b.y};
                unsigned long long z2p[4] = {z2a.x, z2a.y, z2b.x, z2b.y};
#pragma unroll
                for (int g = 0; g < 4; ++g) {
                    ulonglong2 a2 = *(const ulonglong2*)(rowA + aoff[g]);
                    ulonglong2 m2 = *(const ulonglong2*)(rowM + aoff[g]);
#pragma unroll
                    for (int yp = 0; yp < 4; ++yp) {
                        acc[2 * g][yp]     = fma2(a2.x, z2p[yp], acc[2 * g][yp]);
                        acc[2 * g][yp]     = fma2(m2.x, z1p[yp], acc[2 * g][yp]);
                        acc[2 * g + 1][yp] = fma2(a2.y, z2p[yp], acc[2 * g + 1][yp]);
                        acc[2 * g + 1][yp] = fma2(m2.y, z1p[yp], acc[2 * g + 1][yp]);
                    }
                }
            }
        }

        int txL = xlen[b], tyL = ylen[b];
        float bv[8];
        *(float4*)&bv[0] = *(const float4*)&g_bias[b * TX + x0 + xl];
        *(float4*)&bv[4] = *(const float4*)&g_bias[b * TX + x0 + xl + 4];
#pragma unroll
        for (int yy = 0; yy < 8; ++yy) {
            int y = y0 + yl + yy;
            bool yok = (y < tyL);
            int yp = yy >> 1;
            bool hi = (yy & 1);
            float o[8];
#pragma unroll
            for (int j = 0; j < 8; ++j) {
                float2 u = unpack2(acc[j][yp]);
                float v = hi ? u.y : u.x;
                int x = x0 + xl + j;
                o[j] = (yok && x < txL) ? (bv[j] + v) : 0.0f;
            }
            size_t base = ((size_t)b * TY + y) * TX + x0 + xl;
            *(float4*)&g_logp[base]     = make_float4(o[0], o[1], o[2], o[3]);
            *(float4*)&g_logp[base + 4] = make_float4(o[4], o[5], o[6], o[7]);
        }
        // release: make tile visible, then count it
        __threadfence();
        __syncthreads();
        if (tid == 0) atomicAdd(&g_done[b * 8 + tp], 1);
    } else {
        // ================= pre_out role (transposes + attn zero-fill) =================
        float* tile = (float*)msm;   // [80][129]
        int pbid = bid - 16 - GEMM_BLKS;   // 0..495
        if (pbid < 384) {
            int role, idx;
            const float* src;
            int srcN;
            if (pbid < 256)      { role = 0; idx = pbid;       src = z;   srcN = TY; }
            else if (pbid < 320) { role = 1; idx = pbid - 256; src = om;  srcN = TX; }
            else                 { role = 2; idx = pbid - 320; src = ols; srcN = TX; }
            int tilesPerB = (role == 0) ? 16 : 4;
            int b  = idx / tilesPerB;
            int n0 = (idx % tilesPerB) * 128;
            int tyL = ylen[b];
#pragma unroll
            for (int i = 0; i < 5; ++i) {
                int f  = tid + i * 512;
                int c  = f >> 5;
                int s4 = (f & 31) << 2;
                float4 v = *(const float4*)&src[((size_t)b * CC + c) * srcN + n0 + s4];
                int base = c * 129 + s4;
                tile[base]     = v.x;
                tile[base + 1] = v.y;
                tile[base + 2] = v.z;
                tile[base + 3] = v.w;
            }
            __syncthreads();
#pragma unroll
            for (int i = 0; i < 5; ++i) {
                int f  = tid + i * 512;
                int sl = f / 20;
                int c4 = (f % 20) * 4;
                float4 o;
                o.x = tile[(c4 + 0) * 129 + sl];
                o.y = tile[(c4 + 1) * 129 + sl];
                o.z = tile[(c4 + 2) * 129 + sl];
                o.w = tile[(c4 + 3) * 129 + sl];
                int n = n0 + sl;
                if (role == 0) {
                    if (n >= tyL) o = make_float4(0.f, 0.f, 0.f, 0.f);
                    *(float4*)&out[OFF_Z + ((size_t)b * TY + n) * CC + c4] = o;
                } else {
                    float* dst = (role == 1) ? g_omT : g_olsT;
                    *(float4*)&dst[((size_t)b * TX + n) * CC + c4] = o;
                }
            }
        } else {
            size_t total = (size_t)BB * TY * TX / 4;
            float4* p = (float4*)&out[OFF_AT];
            float4 zv = make_float4(0.f, 0.f, 0.f, 0.f);
            size_t start = (size_t)(pbid - 384) * 512 + tid;
            for (size_t i = start; i < total; i += (size_t)NFILL * 512)
                p[i] = zv;
        }
    }
}

// ---------------- kernel 3: gathers + attn ones ----------------
__global__ void __launch_bounds__(256) gather_kernel(float* __restrict__ out) {
    int t = blockIdx.x * 256 + threadIdx.x;
    if (t >= BB * TY * 20) return;
    int bs = t / 20;
    int c4 = (t % 20) * 4;
    int b  = bs >> 11;
    int xs = g_xs[bs];
    float4 m = make_float4(0.f, 0.f, 0.f, 0.f), l = m;
    if (xs >= 0) {
        size_t rb = ((size_t)b * TX + xs) * CC + c4;
        m = *(const float4*)&g_omT[rb];
        l = *(const float4*)&g_olsT[rb];
        if (c4 == 0) out[OFF_AT + (size_t)bs * TX + xs] = 1.0f;
    }
    *(float4*)&out[OFF_M + (size_t)bs * CC + c4] = m;
    *(float4*)&out[OFF_L + (size_t)bs * CC + c4] = l;
}

// ---------------- launch ----------------
extern "C" void kernel_launch(void* const* d_in, const int* in_sizes, int n_in,
                              void* d_out, int out_size) {
    const float* om   = (const float*)d_in[0];
    const float* ols  = (const float*)d_in[1];
    const float* z    = (const float*)d_in[2];
    const int*   xlen = (const int*)d_in[3];
    const int*   ylen = (const int*)d_in[4];
    float* out = (float*)d_out;

    static bool attr_set = false;
    if (!attr_set) {
        cudaFuncSetAttribute(mega_kernel, cudaFuncAttributeMaxDynamicSharedMemorySize, MEGA_SMEM);
        attr_set = true;
    }

    prep_kernel<<<dim3(TX / 128, BB), 128>>>(om, ols);
    mega_kernel<<<16 + GEMM_BLKS + PRE_BLKS, 512, MEGA_SMEM>>>(z, om, ols, xlen, ylen, out);
    gather_kernel<<<(BB * TY * 20 + 255) / 256, 256>>>(out);
}

// round 15
// speedup vs baseline: 1.4583x; 1.1596x over previous
#include <cuda_runtime.h>
#include <cstdint>

#define BB 16
#define CC 80
#define TX 512
#define TY 2048
#define NEGF (-1000000000.0f)

// Output layout (flat concat, fp32):
// z_T [B,TY,C], y_mean_T [B,TY,C], y_ls_T [B,TY,C], attn_T [B,TY,TX], dur [B,TX,1]
#define N_ZT   ((size_t)BB * TY * CC)
#define OFF_Z   ((size_t)0)
#define OFF_M   (N_ZT)
#define OFF_L   (2 * N_ZT)
#define OFF_AT  (3 * N_ZT)
#define OFF_DUR (3 * N_ZT + (size_t)BB * TY * TX)

// ---------------- scratch ----------------
__device__ float g_a   [BB * CC * TX];
__device__ float g_ms  [BB * CC * TX];
__device__ float g_bias[BB * TX];
__device__ float g_logp[(size_t)BB * TY * TX];
__device__ int   g_xs  [BB * TY];
__device__ float g_omT [BB * TX * CC];   // [b][x][c]
__device__ float g_olsT[BB * TX * CC];
__device__ int   g_done[BB * 8];         // per-(batch, 256-row ytile-pair) x-tile completion

// ---------------- f32x2 helpers ----------------
__device__ __forceinline__ unsigned long long pack2(float lo, float hi) {
    unsigned long long r;
    asm("mov.b64 %0, {%1, %2};" : "=l"(r) : "f"(lo), "f"(hi));
    return r;
}
__device__ __forceinline__ float2 unpack2(unsigned long long v) {
    float lo, hi;
    asm("mov.b64 {%0, %1}, %2;" : "=f"(lo), "=f"(hi) : "l"(v));
    return make_float2(lo, hi);
}
__device__ __forceinline__ unsigned long long fma2(unsigned long long a,
                                                   unsigned long long b,
                                                   unsigned long long c) {
    unsigned long long d;
    asm("fma.rn.f32x2 %0, %1, %2, %3;" : "=l"(d) : "l"(a), "l"(b), "l"(c));
    return d;
}
__device__ __forceinline__ unsigned swz(unsigned b) {
    return b ^ ((b >> 3) & 0x70u);
}
__device__ __forceinline__ void cp16cg(unsigned smem_addr, const void* gptr) {
    asm volatile("cp.async.cg.shared.global [%0], [%1], 16;\n"
                 :: "r"(smem_addr), "l"(gptr));
}
#define CP_COMMIT() asm volatile("cp.async.commit_group;\n" ::: "memory")
#define CP_WAIT(n)  asm volatile("cp.async.wait_group %0;\n" :: "n"(n) : "memory")

// acquire-spin until 256-row ytile-pair tp of batch b has all 4 x-tiles done
__device__ __forceinline__ void wait_pair(int b, int tp, int& tp_seen) {
    if (tp <= tp_seen) return;
    volatile int* p = &g_done[b * 8 + tp];
    while (*p < 4) __nanosleep(200);
    __threadfence();
    tp_seen = tp;
}

// ---------------- kernel 1: prep (4-way channel split + zero done counters) ----------------
__global__ void __launch_bounds__(512) prep_kernel(const float* __restrict__ om,
                                                   const float* __restrict__ ols) {
    __shared__ float pbs[4][128];
    int b = blockIdx.y;
    int tid = threadIdx.x;
    int cg = tid >> 7;           // 0..3 channel group
    int xl = tid & 127;
    int x = blockIdx.x * 128 + xl;
    if (blockIdx.x == 0 && blockIdx.y == 0 && tid < 128)
        g_done[tid] = 0;
    float acc = 0.0f;
#pragma unroll 4
    for (int c = cg * 20; c < cg * 20 + 20; ++c) {
        size_t i = ((size_t)b * CC + c) * TX + x;
        float ls = ols[i];
        float m  = om[i];
        float a  = expf(-2.0f * ls);
        g_a[i]  = a;
        g_ms[i] = m * a;
        acc += -0.9189385332046727f - ls - 0.5f * m * m * a;
    }
    pbs[cg][xl] = acc;
    __syncthreads();
    if (cg == 0)
        g_bias[b * TX + x] = pbs[0][xl] + pbs[1][xl] + pbs[2][xl] + pbs[3][xl];
}

// ---------------- kernel 2: MEGA (DP blocks + gemm blocks + pre_out blocks) ----------------
// DP smem: sd[TY/8][128] u32 128KB | bndw[4][64] 1KB | sxs[TY] 8KB | ring[16][128] f4 32KB
// gemm smem: A 16K | M 16K | Z1 16K | Z2 16K (64KB)
// pre_out smem: tile[80*129] f32 (~41KB)
#define DPW 4
#define CHUNK 16
#define RINGC 16
#define SD_WORDS (TY / 8 * 128)
#define MEGA_SMEM (SD_WORDS * 4 + DPW * 64 * 4 + TY * 4 + RINGC * 128 * 16)
#define NFILL 112
#define GEMM_BLKS 512                     // 8 typairs x 16 b x 4 xtiles
#define PRE_BLKS 496

__global__ void __launch_bounds__(512, 1) mega_kernel(const float* __restrict__ z,
                                                      const float* __restrict__ om,
                                                      const float* __restrict__ ols,
                                                      const int* __restrict__ xlen,
                                                      const int* __restrict__ ylen,
                                                      float* __restrict__ out) {
    extern __shared__ __align__(16) unsigned char msm[];
    int bid = blockIdx.x;
    int tid = threadIdx.x;

    if (bid < 16) {
        // ================= DP role (threads 0..127 run the systolic loop) =================
        unsigned* sd = (unsigned*)msm;                                     // [TY/8][128]
        float* bndw = (float*)(msm + (size_t)SD_WORDS * 4);                // [DPW][64]
        int* sxs = (int*)(msm + (size_t)SD_WORDS * 4 + DPW * 64 * 4);      // [TY]
        float4* ring = (float4*)(msm + (size_t)SD_WORDS * 4 + DPW * 64 * 4 + TY * 4);

        int b = bid;
        int w = tid >> 5, lane = tid & 31;
        const float4* lp4 = (const float4*)&g_logp[(size_t)b * TY * TX];
        int gx0 = tid * 4;
        float* mybnd = bndw + w * 64;
        const float* pbnd = bndw + (w - 1) * 64;
        int tyL = ylen[b];
        int nch = (tyL + CHUNK - 1) / CHUNK;
        int tp_max = (tyL - 1) >> 8;

        if (tid < 128) {
            unsigned rbase = (unsigned)__cvta_generic_to_shared(ring) + tid * 16;
            int tp_seen = -1;
            wait_pair(b, 0, tp_seen);
            // prime: 2 groups of 8 columns
#pragma unroll
            for (int d = 0; d < 2; ++d) {
#pragma unroll
                for (int q = 0; q < 8; ++q)
                    cp16cg(rbase + (d * 8 + q) * 2048, &lp4[(d * 8 + q) * 128 + tid]);
                CP_COMMIT();
            }

            float r0 = NEGF, r1 = NEGF, r2 = NEGF, r3 = NEGF;
            unsigned nib = 0;

            for (int c = 0; c < nch; ++c) {
                int tp_need = (c * CHUNK + 31) >> 8;
                if (tp_need > tp_max) tp_need = tp_max;
                wait_pair(b, tp_need, tp_seen);
                if (w > 0) asm volatile("bar.sync %0, 64;" :: "r"(8 + w));
#pragma unroll
                for (int g = 0; g < 2; ++g) {
                    int y0 = c * CHUNK + g * 8;
                    CP_WAIT(1);
                    float4 cc[8];
#pragma unroll
                    for (int q = 0; q < 8; ++q)
                        cc[q] = ring[((y0 + q) & (RINGC - 1)) * 128 + tid];
                    float pb[8];
#pragma unroll
                    for (int q = 0; q < 8; ++q) {
                        int yi = y0 + q - 1;
                        pb[q] = (w > 0 && yi >= 0) ? pbnd[yi & 63] : NEGF;
                    }
                    if (y0 + RINGC < TY) {
#pragma unroll
                        for (int q = 0; q < 8; ++q)
                            cp16cg(rbase + ((y0 + q) & (RINGC - 1)) * 2048,
                                   &lp4[(size_t)(y0 + RINGC + q) * 128 + tid]);
                    }
                    CP_COMMIT();
#pragma unroll
                    for (int j = 0; j < 8; ++j) {
                        int y = y0 + j;
                        if (y == 0) {
                            r0 = (gx0 == 0) ? cc[0].x : NEGF;
                            r1 = r2 = r3 = NEGF;
                            if (lane == 31) mybnd[0] = r3;
                        } else {
                            float ls = __shfl_up_sync(0xffffffffu, r3, 1);   // issued first
                            bool c3 = r2 > r3; r3 = cc[j].w + fmaxf(r3, r2);
                            bool c2 = r1 > r2; r2 = cc[j].z + fmaxf(r2, r1);
                            bool c1 = r0 > r1; r1 = cc[j].y + fmaxf(r1, r0);
                            float left = (lane == 0) ? pb[j] : ls;           // consume late
                            bool c0 = left > r0;
                            r0 = cc[j].x + fmaxf(r0, left);
                            unsigned nb = (c0 ? 1u : 0u) | (c1 ? 2u : 0u) |
                                          (c2 ? 4u : 0u) | (c3 ? 8u : 0u);
                            if (j == 0) {
                                nib |= nb << 28;
                                sd[((y - 1) >> 3) * 128 + tid] = nib;
                                nib = 0;
                            } else {
                                nib |= nb << ((j - 1) * 4);
                            }
                            if (lane == 31) mybnd[y & 63] = r3;
                        }
                    }
                }
                if (w < DPW - 1) asm volatile("bar.sync %0, 64;" :: "r"(9 + w));
            }
            // final partial word (decisions for the tail of the last chunk)
            sd[(nch * 2 - 1) * 128 + tid] = nib;
        }
        __syncthreads();

        int txL = xlen[b];
        if (tid == 0) {
            int idx = txL - 1;
            int y = tyL - 1;
            unsigned wcur = sd[(((y - 1) >= 0 ? (y - 1) : 0) >> 3) * 128 + (idx >> 2)];
            for (; y >= 0; --y) {
                sxs[y] = idx;
                int mv = 0;
                if (idx > 0) {
                    if (idx == y) mv = 1;
                    else mv = (wcur >> (((y - 1) & 7) * 4 + (idx & 3))) & 1;
                }
                idx -= mv;
                int yn = (y - 2) >= 0 ? (y - 2) : 0;
                wcur = sd[(yn >> 3) * 128 + (idx >> 2)];   // prefetch next step's word
            }
        }
        __syncthreads();
        // publish xs (512 threads)
        for (int y = tid; y < tyL; y += 512) g_xs[b * TY + y] = sxs[y];
        for (int y = tyL + tid; y < TY; y += 512) g_xs[b * TY + y] = -1;
        // durations via binary search over monotone sxs[0..tyL); one x per thread
        {
            int x = tid;
            float dv = 0.0f;
            if (x < txL) {
                int lo = 0, hi = tyL;
                while (lo < hi) { int mid = (lo + hi) >> 1; if (sxs[mid] < x) lo = mid + 1; else hi = mid; }
                int start = lo;
                hi = tyL;
                while (lo < hi) { int mid = (lo + hi) >> 1; if (sxs[mid] < x + 1) lo = mid + 1; else hi = mid; }
                dv = log1pf((float)(lo - start));
            }
            out[OFF_DUR + b * TX + x] = dv;
        }
    } else if (bid < 16 + GEMM_BLKS) {
        // ================= gemm role (512 thr, 128x x 256y tile, typair-outermost) ==========
        unsigned char* smA  = msm;
        unsigned char* smM  = msm + 16384;
        unsigned char* smZ1 = msm + 32768;
        unsigned char* smZ2 = msm + 49152;

        int bid2 = bid - 16;
        int tp = bid2 >> 6;            // 0..7  (all batches' typair 0 first)
        int b  = (bid2 >> 2) & 15;
        int x0 = (bid2 & 3) * 128;
        int y0 = tp * 256;
        int txL = xlen[b], tyL = ylen[b];

        // tile entirely outside the valid region: nothing downstream reads it
        if (x0 >= txL || y0 >= tyL) {
            __syncthreads();
            if (tid == 0) atomicAdd(&g_done[b * 8 + tp], 1);
            return;
        }

        int txi = tid & 15;            // 16 x-groups of 8
        int tyi = tid >> 4;            // 32 y-groups of 8
        int xl = txi * 8;
        int yl = tyi * 8;

        unsigned aoff[4];
#pragma unroll
        for (int g = 0; g < 4; ++g) aoff[g] = swz((unsigned)(txi * 64 + g * 16));
        unsigned zoff = (unsigned)(tyi * 32);

        unsigned long long acc[8][4];
#pragma unroll
        for (int i = 0; i < 8; ++i)
#pragma unroll
            for (int j = 0; j < 4; ++j) acc[i][j] = 0ULL;

        for (int kc = 0; kc < CC; kc += 16) {
            __syncthreads();
            // A/M: 16 rows x 128 x = 512 float4; 1 per thread
            {
                int f  = tid;
                int r  = f >> 5;
                int c4 = (f & 31) << 2;
                size_t gi = ((size_t)b * CC + kc + r) * TX + x0 + c4;
                float4 av = *(const float4*)&g_a[gi];
                float4 mv = *(const float4*)&g_ms[gi];
                unsigned sb0 = swz((unsigned)(c4 * 8));
                unsigned sb1 = swz((unsigned)(c4 * 8 + 16));
                *(ulonglong2*)(smA + r * 1024 + sb0) = make_ulonglong2(pack2(av.x, av.x), pack2(av.y, av.y));
                *(ulonglong2*)(smA + r * 1024 + sb1) = make_ulonglong2(pack2(av.z, av.z), pack2(av.w, av.w));
                *(ulonglong2*)(smM + r * 1024 + sb0) = make_ulonglong2(pack2(mv.x, mv.x), pack2(mv.y, mv.y));
                *(ulonglong2*)(smM + r * 1024 + sb1) = make_ulonglong2(pack2(mv.z, mv.z), pack2(mv.w, mv.w));
            }
            // Z: 16 rows x 256 y = 1024 float4; 2 per thread
#pragma unroll
            for (int i = 0; i < 2; ++i) {
                int f  = tid + i * 512;
                int r  = f >> 6;
                int c4 = (f & 63) << 2;
                size_t gi = ((size_t)b * CC + kc + r) * TY + y0 + c4;
                float4 zv = *(const float4*)&z[gi];
                ulonglong2* p1 = (ulonglong2*)(smZ1 + r * 1024 + (f & 63) * 16);
                ulonglong2* p2 = (ulonglong2*)(smZ2 + r * 1024 + (f & 63) * 16);
                *p1 = make_ulonglong2(pack2(zv.x, zv.y), pack2(zv.z, zv.w));
                *p2 = make_ulonglong2(pack2(-0.5f * zv.x * zv.x, -0.5f * zv.y * zv.y),
                                      pack2(-0.5f * zv.z * zv.z, -0.5f * zv.w * zv.w));
            }
            __syncthreads();
#pragma unroll
            for (int k = 0; k < 16; ++k) {
                const unsigned char* rowA = smA + k * 1024;
                const unsigned char* rowM = smM + k * 1024;
                ulonglong2 z1a = *(const ulonglong2*)(smZ1 + k * 1024 + zoff);
                ulonglong2 z1b = *(const ulonglong2*)(smZ1 + k * 1024 + zoff + 16);
                ulonglong2 z2a = *(const ulonglong2*)(smZ2 + k * 1024 + zoff);
                ulonglong2 z2b = *(const ulonglong2*)(smZ2 + k * 1024 + zoff + 16);
                unsigned long long z1p[4] = {z1a.x, z1a.y, z1b.x, z1b.y};
                unsigned long long z2p[4] = {z2a.x, z2a.y, z2b.x, z2b.y};
#pragma unroll
                for (int g = 0; g < 4; ++g) {
                    ulonglong2 a2 = *(const ulonglong2*)(rowA + aoff[g]);
                    ulonglong2 m2 = *(const ulonglong2*)(rowM + aoff[g]);
#pragma unroll
                    for (int yp = 0; yp < 4; ++yp) {
                        acc[2 * g][yp]     = fma2(a2.x, z2p[yp], acc[2 * g][yp]);
                        acc[2 * g][yp]     = fma2(m2.x, z1p[yp], acc[2 * g][yp]);
                        acc[2 * g + 1][yp] = fma2(a2.y, z2p[yp], acc[2 * g + 1][yp]);
                        acc[2 * g + 1][yp] = fma2(m2.y, z1p[yp], acc[2 * g + 1][yp]);
                    }
                }
            }
        }

        float bv[8];
        *(float4*)&bv[0] = *(const float4*)&g_bias[b * TX + x0 + xl];
        *(float4*)&bv[4] = *(const float4*)&g_bias[b * TX + x0 + xl + 4];
#pragma unroll
        for (int yy = 0; yy < 8; ++yy) {
            int y = y0 + yl + yy;
            bool yok = (y < tyL);
            int yp = yy >> 1;
            bool hi = (yy & 1);
            float o[8];
#pragma unroll
            for (int j = 0; j < 8; ++j) {
                float2 u = unpack2(acc[j][yp]);
                float v = hi ? u.y : u.x;
                int x = x0 + xl + j;
                o[j] = (yok && x < txL) ? (bv[j] + v) : 0.0f;
            }
            size_t base = ((size_t)b * TY + y) * TX + x0 + xl;
            *(float4*)&g_logp[base]     = make_float4(o[0], o[1], o[2], o[3]);
            *(float4*)&g_logp[base + 4] = make_float4(o[4], o[5], o[6], o[7]);
        }
        // release: make tile visible, then count it
        __threadfence();
        __syncthreads();
        if (tid == 0) atomicAdd(&g_done[b * 8 + tp], 1);
    } else {
        // ================= pre_out role (transposes + attn zero-fill) =================
        float* tile = (float*)msm;   // [80][129]
        int pbid = bid - 16 - GEMM_BLKS;   // 0..495
        if (pbid < 384) {
            int role, idx;
            const float* src;
            int srcN;
            if (pbid < 256)      { role = 0; idx = pbid;       src = z;   srcN = TY; }
            else if (pbid < 320) { role = 1; idx = pbid - 256; src = om;  srcN = TX; }
            else                 { role = 2; idx = pbid - 320; src = ols; srcN = TX; }
            int tilesPerB = (role == 0) ? 16 : 4;
            int b  = idx / tilesPerB;
            int n0 = (idx % tilesPerB) * 128;
            int tyL = ylen[b];
#pragma unroll
            for (int i = 0; i < 5; ++i) {
                int f  = tid + i * 512;
                int c  = f >> 5;
                int s4 = (f & 31) << 2;
                float4 v = *(const float4*)&src[((size_t)b * CC + c) * srcN + n0 + s4];
                int base = c * 129 + s4;
                tile[base]     = v.x;
                tile[base + 1] = v.y;
                tile[base + 2] = v.z;
                tile[base + 3] = v.w;
            }
            __syncthreads();
#pragma unroll
            for (int i = 0; i < 5; ++i) {
                int f  = tid + i * 512;
                int sl = f / 20;
                int c4 = (f % 20) * 4;
                float4 o;
                o.x = tile[(c4 + 0) * 129 + sl];
                o.y = tile[(c4 + 1) * 129 + sl];
                o.z = tile[(c4 + 2) * 129 + sl];
                o.w = tile[(c4 + 3) * 129 + sl];
                int n = n0 + sl;
                if (role == 0) {
                    if (n >= tyL) o = make_float4(0.f, 0.f, 0.f, 0.f);
                    *(float4*)&out[OFF_Z + ((size_t)b * TY + n) * CC + c4] = o;
                } else {
                    float* dst = (role == 1) ? g_omT : g_olsT;
                    *(float4*)&dst[((size_t)b * TX + n) * CC + c4] = o;
                }
            }
        } else {
            size_t total = (size_t)BB * TY * TX / 4;
            float4* p = (float4*)&out[OFF_AT];
            float4 zv = make_float4(0.f, 0.f, 0.f, 0.f);
            size_t start = (size_t)(pbid - 384) * 512 + tid;
            for (size_t i = start; i < total; i += (size_t)NFILL * 512)
                p[i] = zv;
        }
    }
}

// ---------------- kernel 3: gathers + attn ones ----------------
__global__ void __launch_bounds__(256) gather_kernel(float* __restrict__ out) {
    int t = blockIdx.x * 256 + threadIdx.x;
    if (t >= BB * TY * 20) return;
    int bs = t / 20;
    int c4 = (t % 20) * 4;
    int b  = bs >> 11;
    int xs = g_xs[bs];
    float4 m = make_float4(0.f, 0.f, 0.f, 0.f), l = m;
    if (xs >= 0) {
        size_t rb = ((size_t)b * TX + xs) * CC + c4;
        m = *(const float4*)&g_omT[rb];
        l = *(const float4*)&g_olsT[rb];
        if (c4 == 0) out[OFF_AT + (size_t)bs * TX + xs] = 1.0f;
    }
    *(float4*)&out[OFF_M + (size_t)bs * CC + c4] = m;
    *(float4*)&out[OFF_L + (size_t)bs * CC + c4] = l;
}

// ---------------- launch ----------------
extern "C" void kernel_launch(void* const* d_in, const int* in_sizes, int n_in,
                              void* d_out, int out_size) {
    const float* om   = (const float*)d_in[0];
    const float* ols  = (const float*)d_in[1];
    const float* z    = (const float*)d_in[2];
    const int*   xlen = (const int*)d_in[3];
    const int*   ylen = (const int*)d_in[4];
    float* out = (float*)d_out;

    static bool attr_set = false;
    if (!attr_set) {
        cudaFuncSetAttribute(mega_kernel, cudaFuncAttributeMaxDynamicSharedMemorySize, MEGA_SMEM);
        attr_set = true;
    }

    prep_kernel<<<dim3(TX / 128, BB), 512>>>(om, ols);
    mega_kernel<<<16 + GEMM_BLKS + PRE_BLKS, 512, MEGA_SMEM>>>(z, om, ols, xlen, ylen, out);
    gather_kernel<<<(BB * TY * 20 + 255) / 256, 256>>>(out);
}